// round 7
// baseline (speedup 1.0000x reference)
#include <cuda_runtime.h>
#include <cuda_fp16.h>
#include <cuda_bf16.h>

#define FULLMASK 0xffffffffu
#define WPB 4
#define NTH (WPB * 32)
#define RPW 2

#define RADIUS_ 0.1f
#define TH_ 5e-5f
#define BMIN_ -0.15f
#define BMAX_ 0.15f
#define BIGT_ 1e10f

// Forward W2: fp32, lane-major, row stride 132 floats, conflict-free LDS.128
//   W2f[lane][i]      = W2[i][lane]      (za weights)
//   W2f[lane][64+i]   = W2[i][lane+32]   (zb weights)
// Backward W2: fp16 (cold path), lane-major half2, stride 68
struct Shm {
    float buf[WPB][4][64];      // per-warp broadcast buffer (h1 / u)
    float W2f[32][132];
    __half2 W2qt[32][68];
    float W1[3][64];
    float b1[64], b2[64], W3[64];
    float b3;
};

// Per-lane loop-invariant weights held in registers
struct LaneW {
    float w1xa, w1ya, w1za, b1a;
    float w1xb, w1yb, w1zb, b1b;
    float b2a, b2b, w3a, w3b, b3;
};

__device__ __forceinline__ float sp_(float x) {
    return fmaxf(x, 0.f) + __logf(1.f + __expf(-fabsf(x)));
}
__device__ __forceinline__ float sig_(float x) {
    return 1.f / (1.f + __expf(-x));
}
__device__ __forceinline__ float tanh_(float x) {
    float e = __expf(2.f * x);
    return 1.f - 2.f / (e + 1.f);
}
__device__ __forceinline__ float wsum(float v) {
    v += __shfl_xor_sync(FULLMASK, v, 16);
    v += __shfl_xor_sync(FULLMASK, v, 8);
    v += __shfl_xor_sync(FULLMASK, v, 4);
    v += __shfl_xor_sync(FULLMASK, v, 2);
    v += __shfl_xor_sync(FULLMASK, v, 1);
    return v;
}

// Warp-cooperative SDF eval of B points. All lanes get all B results.
template <int B>
__device__ __forceinline__ void sdf_eval(Shm& s, int w, const LaneW& lw,
                                         const float* px, const float* py, const float* pz,
                                         float* outv) {
    const int lane = threadIdx.x & 31;
    float r[B];
    __syncwarp();
#pragma unroll
    for (int b = 0; b < B; b++) {
        r[b] = sqrtf(fmaf(px[b], px[b], fmaf(py[b], py[b], pz[b] * pz[b])) + 1e-12f);
        float za = fmaf(pz[b], lw.w1za, fmaf(py[b], lw.w1ya, fmaf(px[b], lw.w1xa, lw.b1a)));
        float zb = fmaf(pz[b], lw.w1zb, fmaf(py[b], lw.w1yb, fmaf(px[b], lw.w1xb, lw.b1b)));
        s.buf[w][b][lane] = sp_(za);
        s.buf[w][b][lane + 32] = sp_(zb);
    }
    __syncwarp();
    float za[B], zb[B];
#pragma unroll
    for (int b = 0; b < B; b++) { za[b] = lw.b2a; zb[b] = lw.b2b; }
#pragma unroll 2
    for (int i = 0; i < 64; i += 4) {
        float4 wa = *(const float4*)&s.W2f[lane][i];
        float4 wb = *(const float4*)&s.W2f[lane][64 + i];
#pragma unroll
        for (int b = 0; b < B; b++) {
            float4 h = *(const float4*)&s.buf[w][b][i];
            za[b] = fmaf(h.x, wa.x, za[b]); zb[b] = fmaf(h.x, wb.x, zb[b]);
            za[b] = fmaf(h.y, wa.y, za[b]); zb[b] = fmaf(h.y, wb.y, zb[b]);
            za[b] = fmaf(h.z, wa.z, za[b]); zb[b] = fmaf(h.z, wb.z, zb[b]);
            za[b] = fmaf(h.w, wa.w, za[b]); zb[b] = fmaf(h.w, wb.w, zb[b]);
        }
    }
#pragma unroll
    for (int b = 0; b < B; b++) {
        float part = fmaf(sp_(za[b]), lw.w3a, sp_(zb[b]) * lw.w3b);
        float z3 = wsum(part) + lw.b3;
        outv[b] = r[b] - RADIUS_ + 0.01f * tanh_(z3);
    }
}

// Batched normals for 2 points with per-point masks. nrm zeroed where !m.
__device__ __forceinline__ void sdf_normal2(Shm& s, int w, const LaneW& lw,
                                            const float* px, const float* py, const float* pz,
                                            const bool* m, float nrm[RPW][3]) {
    const int lane = threadIdx.x & 31;
#pragma unroll
    for (int r = 0; r < RPW; r++) { nrm[r][0] = 0.f; nrm[r][1] = 0.f; nrm[r][2] = 0.f; }
    if (!(m[0] || m[1])) return;

    float s1a[RPW], s1b[RPW];
    __syncwarp();
#pragma unroll
    for (int r = 0; r < RPW; r++) {
        float za = fmaf(pz[r], lw.w1za, fmaf(py[r], lw.w1ya, fmaf(px[r], lw.w1xa, lw.b1a)));
        float zb = fmaf(pz[r], lw.w1zb, fmaf(py[r], lw.w1yb, fmaf(px[r], lw.w1xb, lw.b1b)));
        s1a[r] = sig_(za); s1b[r] = sig_(zb);
        s.buf[w][r][lane] = sp_(za);
        s.buf[w][r][lane + 32] = sp_(zb);
    }
    __syncwarp();
    float z2a[RPW], z2b[RPW];
#pragma unroll
    for (int r = 0; r < RPW; r++) { z2a[r] = lw.b2a; z2b[r] = lw.b2b; }
#pragma unroll 2
    for (int i = 0; i < 64; i += 4) {
        float4 wa = *(const float4*)&s.W2f[lane][i];
        float4 wb = *(const float4*)&s.W2f[lane][64 + i];
#pragma unroll
        for (int r = 0; r < RPW; r++) {
            float4 h = *(const float4*)&s.buf[w][r][i];
            z2a[r] = fmaf(h.x, wa.x, z2a[r]); z2b[r] = fmaf(h.x, wb.x, z2b[r]);
            z2a[r] = fmaf(h.y, wa.y, z2a[r]); z2b[r] = fmaf(h.y, wb.y, z2b[r]);
            z2a[r] = fmaf(h.z, wa.z, z2a[r]); z2b[r] = fmaf(h.z, wb.z, z2b[r]);
            z2a[r] = fmaf(h.w, wa.w, z2a[r]); z2b[r] = fmaf(h.w, wb.w, z2b[r]);
        }
    }
    float tt[RPW];
    __syncwarp();
#pragma unroll
    for (int r = 0; r < RPW; r++) {
        float part = fmaf(sp_(z2a[r]), lw.w3a, sp_(z2b[r]) * lw.w3b);
        float z3 = wsum(part) + lw.b3;
        tt[r] = tanh_(z3);
        s.buf[w][r][lane] = lw.w3a * sig_(z2a[r]);
        s.buf[w][r][lane + 32] = lw.w3b * sig_(z2b[r]);
    }
    __syncwarp();
    float sa[RPW] = {0.f, 0.f}, sb[RPW] = {0.f, 0.f};
#pragma unroll 2
    for (int j = 0; j < 64; j += 4) {
        uint4 qv = *(const uint4*)&s.W2qt[lane][j];
        float2 q0 = __half22float2(*(const __half2*)&qv.x);
        float2 q1 = __half22float2(*(const __half2*)&qv.y);
        float2 q2 = __half22float2(*(const __half2*)&qv.z);
        float2 q3 = __half22float2(*(const __half2*)&qv.w);
#pragma unroll
        for (int r = 0; r < RPW; r++) {
            float4 u = *(const float4*)&s.buf[w][r][j];
            sa[r] = fmaf(u.x, q0.x, sa[r]); sb[r] = fmaf(u.x, q0.y, sb[r]);
            sa[r] = fmaf(u.y, q1.x, sa[r]); sb[r] = fmaf(u.y, q1.y, sb[r]);
            sa[r] = fmaf(u.z, q2.x, sa[r]); sb[r] = fmaf(u.z, q2.y, sb[r]);
            sa[r] = fmaf(u.w, q3.x, sa[r]); sb[r] = fmaf(u.w, q3.y, sb[r]);
        }
    }
#pragma unroll
    for (int r = 0; r < RPW; r++) {
        if (!m[r]) continue;  // warp-uniform
        float g1a = s1a[r] * sa[r], g1b = s1b[r] * sb[r];
        float gx = wsum(fmaf(lw.w1xa, g1a, lw.w1xb * g1b));
        float gy = wsum(fmaf(lw.w1ya, g1a, lw.w1yb * g1b));
        float gz = wsum(fmaf(lw.w1za, g1a, lw.w1zb * g1b));
        float coef = 0.01f * (1.f - tt[r] * tt[r]);
        float rr = sqrtf(fmaf(px[r], px[r], fmaf(py[r], py[r], pz[r] * pz[r])) + 1e-12f);
        float invr = 1.f / rr;
        float Gx = fmaf(coef, gx, px[r] * invr);
        float Gy = fmaf(coef, gy, py[r] * invr);
        float Gz = fmaf(coef, gz, pz[r] * invr);
        float nn = sqrtf(Gx * Gx + Gy * Gy + Gz * Gz) + 1e-12f;
        float inv = 1.f / nn;
        nrm[r][0] = Gx * inv; nrm[r][1] = Gy * inv; nrm[r][2] = Gz * inv;
    }
}

__device__ __forceinline__ void aabb(float ox, float oy, float oz,
                                     float dx, float dy, float dz,
                                     float& t_near, float& t_far, bool& hit) {
    float ddx = (fabsf(dx) < 1e-9f) ? 1e-9f : dx;
    float ddy = (fabsf(dy) < 1e-9f) ? 1e-9f : dy;
    float ddz = (fabsf(dz) < 1e-9f) ? 1e-9f : dz;
    float ix = 1.f / ddx, iy = 1.f / ddy, iz = 1.f / ddz;
    float t1x = (BMIN_ - ox) * ix, t2x = (BMAX_ - ox) * ix;
    float t1y = (BMIN_ - oy) * iy, t2y = (BMAX_ - oy) * iy;
    float t1z = (BMIN_ - oz) * iz, t2z = (BMAX_ - oz) * iz;
    float tmin = fmaxf(fmaxf(fminf(t1x, t2x), fminf(t1y, t2y)), fminf(t1z, t2z));
    float tmax = fminf(fminf(fmaxf(t1x, t2x), fmaxf(t1y, t2y)), fmaxf(t1z, t2z));
    hit = (tmax >= tmin) && (tmax > 0.f);
    t_near = hit ? fmaxf(tmin, 0.f) : BIGT_;
    t_far = hit ? tmax : BIGT_;
}

__device__ __forceinline__ void refract(float lx, float ly, float lz,
                                        float nx, float ny, float nz,
                                        float eta1, float eta2,
                                        float* t, float& att) {
    float ct = -(lx * nx + ly * ny + lz * nz);
    float ipx = fmaf(nx, ct, lx);
    float ipy = fmaf(ny, ct, ly);
    float ipz = fmaf(nz, ct, lz);
    float k = eta1 / eta2;
    float tpx = k * ipx, tpy = k * ipy, tpz = k * ipz;
    float tpn = tpx * tpx + tpy * tpy + tpz * tpz;
    float c = fminf(fmaxf(tpn, 0.f), 0.999999f);
    float ti = sqrtf(1.f - c);
    float tx = fmaf(-nx, ti, tpx);
    float ty = fmaf(-ny, ti, tpy);
    float tz = fmaf(-nz, ti, tpz);
    float nn = sqrtf(tx * tx + ty * ty + tz * tz) + 1e-10f;
    float inv = 1.f / nn;
    tx *= inv; ty *= inv; tz *= inv;
    float ctt = -(tx * nx + ty * ny + tz * nz);
    float ei = (ctt * eta1 - ct * eta2) / (ctt * eta1 + ct * eta2 + 1e-10f);
    float ep = (ctt * eta2 - ct * eta1) / (ctt * eta2 + ct * eta1 + 1e-10f);
    att = fminf(fmaxf(0.5f * (ei * ei + ep * ep), 0.f), 1.f);
    t[0] = tx; t[1] = ty; t[2] = tz;
}

__device__ __forceinline__ void reflect(float lx, float ly, float lz,
                                        const float* n, float* r) {
    float dn = lx * n[0] + ly * n[1] + lz * n[2];
    float rx = fmaf(-2.f * dn, n[0], lx);
    float ry = fmaf(-2.f * dn, n[1], ly);
    float rz = fmaf(-2.f * dn, n[2], lz);
    float nn = sqrtf(rx * rx + ry * ry + rz * rz) + 1e-10f;
    float inv = 1.f / nn;
    r[0] = rx * inv; r[1] = ry * inv; r[2] = rz * inv;
}

// Per-ray sampler + secant (rare path). Returns has + t_pred.
__device__ __forceinline__ void sampler_secant(Shm& s, int w, const LaneW& lw,
                                               float ox, float oy, float oz,
                                               float dx, float dy, float dz,
                                               float acc_s, float acc_e, bool far_,
                                               bool& has, float& t_pred) {
    const int lane = threadIdx.x & 31;
    float dt = acc_e - acc_s;
    float vlo = 0.f, vhi = 0.f;
#pragma unroll 1
    for (int base = 0; base < 64; base += 4) {
        float px[4], py[4], pz[4], v[4];
#pragma unroll
        for (int j = 0; j < 4; j++) {
            float tt = fmaf((float)(base + j) * (1.f / 63.f), dt, acc_s);
            px[j] = fmaf(tt, dx, ox);
            py[j] = fmaf(tt, dy, oy);
            pz[j] = fmaf(tt, dz, oz);
        }
        sdf_eval<4>(s, w, lw, px, py, pz, v);
#pragma unroll
        for (int j = 0; j < 4; j++) {
            int k = base + j;
            if (lane == k) vlo = v[j];
            if (lane == k - 32) vhi = v[j];
        }
    }
    unsigned mlo = __ballot_sync(FULLMASK, vlo < 0.f);
    unsigned mhi = __ballot_sync(FULLMASK, vhi < 0.f);
    unsigned long long m = (((unsigned long long)mhi) << 32) | (unsigned long long)mlo;
    bool any = (m != 0ull);
    int ia, ib;
    if (!far_) {
        int idx = any ? (__ffsll((long long)m) - 1) : 0;
        has = any && (idx > 0);
        ia = (idx > 0) ? idx - 1 : 0;
        ib = idx;
    } else {
        int ln = any ? (63 - __clzll((long long)m)) : 63;
        has = any && (ln < 63);
        ia = ln;
        ib = (ln + 1 > 63) ? 63 : ln + 1;
    }
    float f_a = (ia < 32) ? __shfl_sync(FULLMASK, vlo, ia) : __shfl_sync(FULLMASK, vhi, ia - 32);
    float f_b = (ib < 32) ? __shfl_sync(FULLMASK, vlo, ib) : __shfl_sync(FULLMASK, vhi, ib - 32);
    float t_a = fmaf((float)ia * (1.f / 63.f), dt, acc_s);
    float t_b = fmaf((float)ib * (1.f / 63.f), dt, acc_s);
#pragma unroll 1
    for (int it = 0; it < 8; ++it) {
        float den = f_b - f_a;
        if (fabsf(den) < 1e-12f) den = 1e-12f;
        float t_mid = t_a - f_a * (t_b - t_a) / den;
        float px = fmaf(t_mid, dx, ox), py = fmaf(t_mid, dy, oy), pz = fmaf(t_mid, dz, oz);
        float fm;
        sdf_eval<1>(s, w, lw, &px, &py, &pz, &fm);
        bool same = (fm > 0.f) == (f_a > 0.f);
        if (same) { t_a = t_mid; f_a = fm; }
        else      { t_b = t_mid; f_b = fm; }
    }
    float den = f_b - f_a;
    if (fabsf(den) < 1e-12f) den = 1e-12f;
    t_pred = t_a - f_a * (t_b - t_a) / den;
}

// 2-ray merged intersection (one SDF pass).
__device__ __forceinline__ void intersect2(Shm& s, int w, const LaneW& lw,
                                           const float* ox, const float* oy, const float* oz,
                                           const float* dx, const float* dy, const float* dz,
                                           const bool* mask, const float* tn, const float* tf,
                                           bool far_,
                                           bool* valid, float* depth, float nrm[RPW][3]) {
    float acc_s[RPW], acc_e[RPW];
    bool unf_s[RPW], unf_e[RPW];
#pragma unroll
    for (int r = 0; r < RPW; r++) {
        acc_s[r] = mask[r] ? tn[r] : 0.f;
        acc_e[r] = mask[r] ? tf[r] : 0.f;
        unf_s[r] = false; unf_e[r] = false;
    }
    if (mask[0] || mask[1]) {
        float px[4], py[4], pz[4], v[4];
#pragma unroll
        for (int r = 0; r < RPW; r++) {
            px[2*r]   = fmaf(acc_s[r], dx[r], ox[r]);
            py[2*r]   = fmaf(acc_s[r], dy[r], oy[r]);
            pz[2*r]   = fmaf(acc_s[r], dz[r], oz[r]);
            px[2*r+1] = fmaf(acc_e[r], dx[r], ox[r]);
            py[2*r+1] = fmaf(acc_e[r], dy[r], oy[r]);
            pz[2*r+1] = fmaf(acc_e[r], dz[r], oz[r]);
        }
        sdf_eval<4>(s, w, lw, px, py, pz, v);
#pragma unroll
        for (int r = 0; r < RPW; r++) {
            unf_s[r] = mask[r] && (fabsf(v[2*r]) > TH_);
            unf_e[r] = mask[r] && (fabsf(v[2*r+1]) > TH_);
        }
#pragma unroll 1
        for (int it = 0; it < 15; ++it) {
            if (!(unf_s[0] || unf_e[0] || unf_s[1] || unf_e[1])) break;
#pragma unroll
            for (int r = 0; r < RPW; r++) {
                px[2*r]   = fmaf(acc_s[r], dx[r], ox[r]);
                py[2*r]   = fmaf(acc_s[r], dy[r], oy[r]);
                pz[2*r]   = fmaf(acc_s[r], dz[r], oz[r]);
                px[2*r+1] = fmaf(acc_e[r], dx[r], ox[r]);
                py[2*r+1] = fmaf(acc_e[r], dy[r], oy[r]);
                pz[2*r+1] = fmaf(acc_e[r], dz[r], oz[r]);
            }
            sdf_eval<4>(s, w, lw, px, py, pz, v);
#pragma unroll
            for (int r = 0; r < RPW; r++) {
                if (unf_s[r]) acc_s[r] += v[2*r];
                if (unf_e[r]) acc_e[r] -= v[2*r+1];
                bool nc = acc_s[r] < acc_e[r];
                unf_s[r] = unf_s[r] && (fabsf(v[2*r]) > TH_) && nc;
                unf_e[r] = unf_e[r] && (fabsf(v[2*r+1]) > TH_) && nc;
            }
        }
    }
#pragma unroll
    for (int r = 0; r < RPW; r++) {
        bool net = acc_s[r] < acc_e[r];
        bool smask = far_ ? unf_e[r] : unf_s[r];
        if (smask) {  // warp-uniform, rare
            bool has; float t_pred;
            sampler_secant(s, w, lw, ox[r], oy[r], oz[r], dx[r], dy[r], dz[r],
                           acc_s[r], acc_e[r], far_, has, t_pred);
            depth[r] = t_pred;
            net = has;
        } else {
            depth[r] = far_ ? acc_e[r] : acc_s[r];
        }
        valid[r] = net && mask[r];
    }
    float hx[RPW], hy[RPW], hz[RPW];
#pragma unroll
    for (int r = 0; r < RPW; r++) {
        hx[r] = fmaf(depth[r], dx[r], ox[r]);
        hy[r] = fmaf(depth[r], dy[r], oy[r]);
        hz[r] = fmaf(depth[r], dz[r], oz[r]);
    }
    sdf_normal2(s, w, lw, hx, hy, hz, valid, nrm);
}

__global__ void __launch_bounds__(NTH)
trace_kernel(const float* __restrict__ go, const float* __restrict__ gd,
             const float* __restrict__ gW1, const float* __restrict__ gb1,
             const float* __restrict__ gW2, const float* __restrict__ gb2,
             const float* __restrict__ gW3, const float* __restrict__ gb3,
             float* __restrict__ out, int N) {
    __shared__ __align__(16) Shm s;
    int tid = threadIdx.x;
    for (int i = tid; i < 192; i += NTH) ((float*)s.W1)[i] = gW1[i];
    for (int i = tid; i < 64; i += NTH) {
        s.b1[i] = gb1[i];
        s.b2[i] = gb2[i];
        s.W3[i] = gW3[i];
    }
    if (tid == 0) s.b3 = gb3[0];
    for (int i = tid; i < 64 * 32; i += NTH) {
        int r = i >> 5, c = i & 31;
        s.W2f[c][r]      = gW2[r * 64 + c];
        s.W2f[c][64 + r] = gW2[r * 64 + c + 32];
        s.W2qt[c][r] = __floats2half2_rn(gW2[c * 64 + r], gW2[(c + 32) * 64 + r]);
    }
    __syncthreads();

    const int lane = tid & 31;
    const int lane2 = lane + 32;
    LaneW lw;
    lw.w1xa = s.W1[0][lane]; lw.w1ya = s.W1[1][lane]; lw.w1za = s.W1[2][lane]; lw.b1a = s.b1[lane];
    lw.w1xb = s.W1[0][lane2]; lw.w1yb = s.W1[1][lane2]; lw.w1zb = s.W1[2][lane2]; lw.b1b = s.b1[lane2];
    lw.b2a = s.b2[lane]; lw.b2b = s.b2[lane2];
    lw.w3a = s.W3[lane]; lw.w3b = s.W3[lane2];
    lw.b3 = s.b3;

    int w = tid >> 5;
    int rbase = (blockIdx.x * WPB + w) * RPW;
    if (rbase >= N) return;

    float ox[RPW], oy[RPW], oz[RPW], dx[RPW], dy[RPW], dz[RPW];
    bool hit[RPW]; float tn[RPW], tf[RPW];
#pragma unroll
    for (int r = 0; r < RPW; r++) {
        int ray = rbase + r;
        ox[r] = go[ray * 3 + 0]; oy[r] = go[ray * 3 + 1]; oz[r] = go[ray * 3 + 2];
        dx[r] = gd[ray * 3 + 0]; dy[r] = gd[ray * 3 + 1]; dz[r] = gd[ray * 3 + 2];
        aabb(ox[r], oy[r], oz[r], dx[r], dy[r], dz[r], tn[r], tf[r], hit[r]);
    }

    bool valid[RPW]; float depth1[RPW]; float n1[RPW][3];
    intersect2(s, w, lw, ox, oy, oz, dx, dy, dz, hit, tn, tf, false, valid, depth1, n1);

    float fpx[RPW], fpy[RPW], fpz[RPW];
    float o2x[RPW], o2y[RPW], o2z[RPW], d2x[RPW], d2y[RPW], d2z[RPW];
    float att1[RPW], lr1[RPW][3];
    bool mask2[RPW]; float tn2[RPW], tf2[RPW];
#pragma unroll
    for (int r = 0; r < RPW; r++) {
        fpx[r] = fmaf(depth1[r], dx[r], ox[r]);
        fpy[r] = fmaf(depth1[r], dy[r], oy[r]);
        fpz[r] = fmaf(depth1[r], dz[r], oz[r]);
        bool inside = (fpx[r] >= BMIN_) && (fpx[r] <= BMAX_) &&
                      (fpy[r] >= BMIN_) && (fpy[r] <= BMAX_) &&
                      (fpz[r] >= BMIN_) && (fpz[r] <= BMAX_);
        float lt1[3];
        refract(dx[r], dy[r], dz[r], n1[r][0], n1[r][1], n1[r][2], 1.0003f, 1.45f, lt1, att1[r]);
        reflect(dx[r], dy[r], dz[r], n1[r], lr1[r]);
        o2x[r] = fpx[r] - lt1[0]; o2y[r] = fpy[r] - lt1[1]; o2z[r] = fpz[r] - lt1[2];
        d2x[r] = lt1[0]; d2y[r] = lt1[1]; d2z[r] = lt1[2];
        bool hit2;
        aabb(o2x[r], o2y[r], o2z[r], d2x[r], d2y[r], d2z[r], tn2[r], tf2[r], hit2);
        mask2[r] = hit2 && inside && valid[r];
    }

    bool valid2[RPW]; float depth2[RPW]; float n2[RPW][3];
    intersect2(s, w, lw, o2x, o2y, o2z, d2x, d2y, d2z, mask2, tn2, tf2, true, valid2, depth2, n2);

    if (lane == 0) {
        float* out_o = out;
        float* out_d = out + 3 * N;
        float* refl_o = out + 6 * N;
        float* refl_d = out + 9 * N;
        float* att_o = out + 12 * N;
        float* fin_o = out + 13 * N;
        float* fp_o = out + 14 * N;
        float* sp_o = out + 17 * N;
#pragma unroll
        for (int r = 0; r < RPW; r++) {
            int ray = rbase + r;
            float spx = fmaf(depth2[r], d2x[r], o2x[r]);
            float spy = fmaf(depth2[r], d2y[r], o2y[r]);
            float spz = fmaf(depth2[r], d2z[r], o2z[r]);
            float lt2[3], att2_unused;
            refract(d2x[r], d2y[r], d2z[r], -n2[r][0], -n2[r][1], -n2[r][2],
                    1.45f, 1.0003f, lt2, att2_unused);
            bool fin = valid[r] && valid2[r];
            if (fin) {
                out_o[ray * 3 + 0] = fmaf(0.1f, lt2[0], spx);
                out_o[ray * 3 + 1] = fmaf(0.1f, lt2[1], spy);
                out_o[ray * 3 + 2] = fmaf(0.1f, lt2[2], spz);
                out_d[ray * 3 + 0] = lt2[0];
                out_d[ray * 3 + 1] = lt2[1];
                out_d[ray * 3 + 2] = lt2[2];
                refl_o[ray * 3 + 0] = fmaf(0.1f, lr1[r][0], fpx[r]);
                refl_o[ray * 3 + 1] = fmaf(0.1f, lr1[r][1], fpy[r]);
                refl_o[ray * 3 + 2] = fmaf(0.1f, lr1[r][2], fpz[r]);
                refl_d[ray * 3 + 0] = lr1[r][0];
                refl_d[ray * 3 + 1] = lr1[r][1];
                refl_d[ray * 3 + 2] = lr1[r][2];
            } else {
                out_o[ray * 3 + 0] = ox[r]; out_o[ray * 3 + 1] = oy[r]; out_o[ray * 3 + 2] = oz[r];
                out_d[ray * 3 + 0] = dx[r]; out_d[ray * 3 + 1] = dy[r]; out_d[ray * 3 + 2] = dz[r];
                refl_o[ray * 3 + 0] = ox[r]; refl_o[ray * 3 + 1] = oy[r]; refl_o[ray * 3 + 2] = oz[r];
                refl_d[ray * 3 + 0] = dx[r]; refl_d[ray * 3 + 1] = dy[r]; refl_d[ray * 3 + 2] = dz[r];
            }
            att_o[ray] = fin ? att1[r] : 0.f;
            fin_o[ray] = fin ? 1.f : 0.f;
            fp_o[ray * 3 + 0] = fpx[r]; fp_o[ray * 3 + 1] = fpy[r]; fp_o[ray * 3 + 2] = fpz[r];
            sp_o[ray * 3 + 0] = spx; sp_o[ray * 3 + 1] = spy; sp_o[ray * 3 + 2] = spz;
        }
    }
}

extern "C" void kernel_launch(void* const* d_in, const int* in_sizes, int n_in,
                              void* d_out, int out_size) {
    const float* o = (const float*)d_in[0];
    const float* d = (const float*)d_in[1];
    const float* W1 = (const float*)d_in[2];
    const float* b1 = (const float*)d_in[3];
    const float* W2 = (const float*)d_in[4];
    const float* b2 = (const float*)d_in[5];
    const float* W3 = (const float*)d_in[6];
    const float* b3 = (const float*)d_in[7];
    int N = in_sizes[0] / 3;
    int blocks = (N + WPB * RPW - 1) / (WPB * RPW);
    trace_kernel<<<blocks, NTH>>>(o, d, W1, b1, W2, b2, W3, b3, (float*)d_out, N);
}